// round 1
// baseline (speedup 1.0000x reference)
#include <cuda_runtime.h>
#include <cuda_bf16.h>

// Problem constants
// targets: (B=64, H=512, W=1024) int32 ; live region = [:64, :64, :1024]
// pc:      (B=64, 1, h=64, w=128) float32
// loss = -(1/N) * sum( t*log(pc) + (1-t)*log1p(-pc) ),  N = 64*64*128 = 524288
// t nonzero only for (i<8, j<8) corner, value = cond[i,j] broadcast over batch.

#define N_PC 524288
#define N_PC4 131072           // N_PC / 4
#define LOSS_BLOCKS 512        // 512 * 256 * 4 = 524288 exactly

__device__ int           g_counts[64];
__device__ double        g_loss;
__device__ unsigned int  g_done;

__global__ void zero_kernel() {
    int t = threadIdx.x;
    if (t < 64) g_counts[t] = 0;
    if (t == 64) { g_loss = 0.0; g_done = 0u; }
}

// One block per (r, c) row of the live targets corner: r, c in [0, 64).
// Each row is 1024 int32 = 256 int4; 256 threads -> one int4 each.
__global__ __launch_bounds__(256) void count_kernel(const int4* __restrict__ tg) {
    const int blk = blockIdx.x;       // 0..4095
    const int r = blk >> 6;           // 0..63
    const int c = blk & 63;           // 0..63
    // int4 base: r * (512*1024/4) + c * (1024/4)
    const int4* row = tg + (size_t)r * 131072u + (size_t)c * 256u;
    int4 v = row[threadIdx.x];
    int cnt = (v.x == 2) + (v.y == 2) + (v.z == 2) + (v.w == 2);

    #pragma unroll
    for (int o = 16; o > 0; o >>= 1)
        cnt += __shfl_down_sync(0xffffffffu, cnt, o);

    __shared__ int sp[8];
    const int wid = threadIdx.x >> 5;
    const int lid = threadIdx.x & 31;
    if (lid == 0) sp[wid] = cnt;
    __syncthreads();
    if (threadIdx.x == 0) {
        int s = 0;
        #pragma unroll
        for (int k = 0; k < 8; k++) s += sp[k];
        atomicAdd(&g_counts[(r >> 3) * 8 + (c >> 3)], s);
    }
}

// 512 blocks x 256 threads, one float4 of pc per thread (exact cover).
// Corner elements (i<8, j<8 within the 64x128 spatial map) use the cond LUT.
__global__ __launch_bounds__(256) void loss_kernel(const float4* __restrict__ pc,
                                                   float* __restrict__ out) {
    __shared__ float s_cond[64];
    __shared__ float sp[8];
    if (threadIdx.x < 64) {
        int cnt = g_counts[threadIdx.x];
        s_cond[threadIdx.x] = (cnt > 0 && cnt < 64) ? 1.0f : 0.0f;
    }
    __syncthreads();

    const int idx = blockIdx.x * 256 + threadIdx.x;  // 0..131071
    float4 v = pc[idx];

    const int e   = idx << 2;        // element index
    const int rem = e & 8191;        // within one (h*w)=8192 spatial slab
    const int i   = rem >> 7;        // 0..63
    const int j0  = rem & 127;       // multiple of 4

    float sum;
    if (i < 8 && j0 < 8) {
        float vals[4] = { v.x, v.y, v.z, v.w };
        float acc = 0.0f;
        #pragma unroll
        for (int k = 0; k < 4; k++) {
            float t = s_cond[i * 8 + (j0 + k)];
            acc += t * __logf(vals[k]) + (1.0f - t) * log1pf(-vals[k]);
        }
        sum = acc;
    } else {
        sum = log1pf(-v.x) + log1pf(-v.y) + log1pf(-v.z) + log1pf(-v.w);
    }

    #pragma unroll
    for (int o = 16; o > 0; o >>= 1)
        sum += __shfl_down_sync(0xffffffffu, sum, o);

    const int wid = threadIdx.x >> 5;
    const int lid = threadIdx.x & 31;
    if (lid == 0) sp[wid] = sum;
    __syncthreads();

    if (threadIdx.x == 0) {
        float bs = 0.0f;
        #pragma unroll
        for (int k = 0; k < 8; k++) bs += sp[k];
        atomicAdd(&g_loss, (double)bs);
        __threadfence();
        unsigned int d = atomicAdd(&g_done, 1u);
        if (d == (unsigned int)(gridDim.x - 1)) {
            double total = atomicAdd(&g_loss, 0.0);  // acquire-style read
            out[0] = (float)(-total / (double)N_PC);
        }
    }
}

extern "C" void kernel_launch(void* const* d_in, const int* in_sizes, int n_in,
                              void* d_out, int out_size) {
    // metadata order: pc (float32, 524288), targets (int32, 33554432).
    // Pick by size to be robust to ordering.
    const float* pc;
    const int*   tg;
    if (in_sizes[0] == N_PC) {
        pc = (const float*)d_in[0];
        tg = (const int*)  d_in[1];
    } else {
        pc = (const float*)d_in[1];
        tg = (const int*)  d_in[0];
    }
    float* out = (float*)d_out;

    zero_kernel<<<1, 128>>>();
    count_kernel<<<4096, 256>>>((const int4*)tg);
    loss_kernel<<<LOSS_BLOCKS, 256>>>((const float4*)pc, out);
}

// round 2
// speedup vs baseline: 1.2845x; 1.2845x over previous
#include <cuda_runtime.h>
#include <cuda_bf16.h>

// targets: (64, 512, 1024) int32; live region = [:64, :64, :] (16 MiB)
// pc:      (64, 1, 64, 128) float32 (2 MiB)
// loss = -(1/N) * sum( t*log(pc) + (1-t)*log1p(-pc) ), N = 524288
//      = -(1/N) * [ sum log1p(-pc)  +  sum_corner cond(i,j)*(log pc - log1p(-pc)) ]
// cond(i,j) = (0 < count_ij < 64), count_ij over the 8x8x1024 patch block.

#define N_PC    524288
#define GRID    512      // power of two: monotonic done-counter wraps cleanly
#define THREADS 256

__device__ int          g_rowcnt[4096];   // plain stores, overwritten every replay
__device__ float        g_partial[GRID];  // plain stores, overwritten every replay
__device__ unsigned int g_done;           // monotonic arrival counter (zero-init at load)

__global__ __launch_bounds__(THREADS) void fused_kernel(
    const float4* __restrict__ pc4,
    const int4*   __restrict__ tg4,
    const float*  __restrict__ pc,
    float*        __restrict__ out)
{
    const int tid  = threadIdx.x;
    const int bid  = blockIdx.x;
    const int wid  = tid >> 5;
    const int lane = tid & 31;

    // ---- targets count: each warp owns one (r,c) row (1024 ints = 256 int4)
    const int row = bid * 8 + wid;            // 0..4095
    const int r   = row >> 6;                 // 0..63  (batch index)
    const int c   = row & 63;                 // 0..63  (H index)
    const int4* base = tg4 + (size_t)r * 131072u + (size_t)c * 256u;
    int cnt = 0;
    #pragma unroll
    for (int k = 0; k < 8; k++) {
        int4 q = base[lane + k * 32];         // coalesced 512B per warp per k
        cnt += (q.x == 2) + (q.y == 2) + (q.z == 2) + (q.w == 2);
    }
    #pragma unroll
    for (int o = 16; o > 0; o >>= 1)
        cnt += __shfl_down_sync(0xffffffffu, cnt, o);
    if (lane == 0) g_rowcnt[row] = cnt;

    // ---- loss base: one float4 of pc per thread, t=0 form everywhere
    const int idx = bid * THREADS + tid;      // 0..131071
    float4 v = pc4[idx];
    float s = log1pf(-v.x) + log1pf(-v.y) + log1pf(-v.z) + log1pf(-v.w);
    #pragma unroll
    for (int o = 16; o > 0; o >>= 1)
        s += __shfl_down_sync(0xffffffffu, s, o);
    __shared__ float sp[8];
    if (lane == 0) sp[wid] = s;
    __syncthreads();
    if (tid == 0) {
        float bs = 0.0f;
        #pragma unroll
        for (int k = 0; k < 8; k++) bs += sp[k];
        g_partial[bid] = bs;
    }

    // ---- publish + arrive (standard threadFenceReduction pattern)
    __threadfence();
    __syncthreads();
    __shared__ unsigned int s_last;
    if (tid == 0) {
        unsigned int old = atomicAdd(&g_done, 1u);
        s_last = ((old % GRID) == GRID - 1u) ? 1u : 0u;
    }
    __syncthreads();
    if (!s_last) return;
    __threadfence();

    // ================= last block: aggregate everything =================
    __shared__ float  s_cond[64];
    __shared__ double s_red[8];

    // patch counts -> cond
    if (tid < 64) {
        const int i = tid >> 3, j = tid & 7;
        int pcnt = 0;
        #pragma unroll
        for (int rr = 0; rr < 8; rr++)
            #pragma unroll
            for (int cc = 0; cc < 8; cc++)
                pcnt += g_rowcnt[(i * 8 + rr) * 64 + (j * 8 + cc)];
        s_cond[tid] = (pcnt > 0 && pcnt < 64) ? 1.0f : 0.0f;
    }
    __syncthreads();

    // base sum from 512 partials (double)
    double acc = (double)g_partial[tid] + (double)g_partial[tid + THREADS];

    // corner correction: 4096 elements = 64 (i,j) pairs x 64 batches
    {
        const int ij = tid & 63;
        const int i  = ij >> 3, j = ij & 7;
        const float cond = s_cond[ij];
        if (cond != 0.0f) {
            const int b0 = (tid >> 6) * 16;   // 4 thread-groups x 16 batches
            float csum = 0.0f;
            #pragma unroll 4
            for (int b = b0; b < b0 + 16; b++) {
                float p = pc[(size_t)b * 8192u + i * 128 + j];  // L2-hot
                csum += __logf(p) - log1pf(-p);
            }
            acc += (double)csum;
        }
    }

    // block reduce (double)
    #pragma unroll
    for (int o = 16; o > 0; o >>= 1)
        acc += __shfl_down_sync(0xffffffffu, acc, o);
    if (lane == 0) s_red[wid] = acc;
    __syncthreads();
    if (tid == 0) {
        double total = 0.0;
        #pragma unroll
        for (int k = 0; k < 8; k++) total += s_red[k];
        out[0] = (float)(-total / (double)N_PC);
    }
}

extern "C" void kernel_launch(void* const* d_in, const int* in_sizes, int n_in,
                              void* d_out, int out_size) {
    const float* pc;
    const int*   tg;
    if (in_sizes[0] == N_PC) {
        pc = (const float*)d_in[0];
        tg = (const int*)  d_in[1];
    } else {
        pc = (const float*)d_in[1];
        tg = (const int*)  d_in[0];
    }
    fused_kernel<<<GRID, THREADS>>>((const float4*)pc, (const int4*)tg,
                                    pc, (float*)d_out);
}

// round 4
// speedup vs baseline: 1.3905x; 1.0825x over previous
#include <cuda_runtime.h>
#include <cuda_bf16.h>

// targets: (64, 512, 1024) int32; live region = [:64, :64, :] (16 MiB)
// pc:      (64, 1, 64, 128) float32 (2 MiB)
// loss = -(1/N) * [ sum log1p(-pc) + sum_corner cond(i,j)*(log pc - log1p(-pc)) ]
// cond(i,j) = (0 < count_ij < 64); count_ij over targets[8i:8i+8, 8j:8j+8, :].

#define N_PC    524288
#define GRID    1024     // power of two: monotonic done-counter wraps cleanly
#define THREADS 256

__device__ int          g_blkcnt[GRID];   // per-block patch-partial count (plain store)
__device__ float        g_partial[GRID];  // per-block loss partial (plain store)
__device__ unsigned int g_done;           // monotonic arrival counter (zero-init at load)

__global__ __launch_bounds__(THREADS) void fused_kernel(
    const float2* __restrict__ pc2,
    const int4*   __restrict__ tg4,
    const float*  __restrict__ pc,
    float*        __restrict__ out)
{
    const int tid  = threadIdx.x;
    const int bid  = blockIdx.x;
    const int wid  = tid >> 5;
    const int lane = tid & 31;

    // ---- pc loss (t=0 form): one float2 per thread, issued first to overlap
    const int idx = bid * THREADS + tid;            // 0..262143
    float2 v = pc2[idx];

    // ---- targets count: each warp owns a half-row (512 ints = 128 int4)
    const int wg   = bid * 8 + wid;                 // 0..8191
    const int row  = wg >> 1;                       // 0..4095 (= r*64 + c)
    const int half = wg & 1;
    const int4* base = tg4 + (size_t)(row >> 6) * 131072u
                           + (size_t)(row & 63) * 256u
                           + (size_t)half * 128u;
    int4 q0 = base[lane];
    int4 q1 = base[lane + 32];
    int4 q2 = base[lane + 64];
    int4 q3 = base[lane + 96];
    int cnt = (q0.x==2)+(q0.y==2)+(q0.z==2)+(q0.w==2)
            + (q1.x==2)+(q1.y==2)+(q1.z==2)+(q1.w==2)
            + (q2.x==2)+(q2.y==2)+(q2.z==2)+(q2.w==2)
            + (q3.x==2)+(q3.y==2)+(q3.z==2)+(q3.w==2);
    #pragma unroll
    for (int o = 16; o > 0; o >>= 1)
        cnt += __shfl_down_sync(0xffffffffu, cnt, o);

    float s = log1pf(-v.x) + log1pf(-v.y);
    #pragma unroll
    for (int o = 16; o > 0; o >>= 1)
        s += __shfl_down_sync(0xffffffffu, s, o);

    __shared__ float sp[8];
    __shared__ int   sc[8];
    if (lane == 0) { sp[wid] = s; sc[wid] = cnt; }
    __syncthreads();
    if (tid == 0) {
        float bs = 0.0f; int bc = 0;
        #pragma unroll
        for (int k = 0; k < 8; k++) { bs += sp[k]; bc += sc[k]; }
        g_partial[bid] = bs;
        g_blkcnt[bid]  = bc;   // rows 4b..4b+3 all lie in ONE patch (i,j)
    }

    // ---- publish + arrive
    __threadfence();
    __syncthreads();
    __shared__ unsigned int s_last;
    if (tid == 0) {
        unsigned int old = atomicAdd(&g_done, 1u);
        s_last = ((old & (GRID - 1u)) == GRID - 1u) ? 1u : 0u;
    }
    __syncthreads();
    if (!s_last) return;
    __threadfence();

    // ================= last block: aggregate =================
    __shared__ float  s_cond[64];
    __shared__ double s_red[8];

    // patch counts -> cond. Patch (i,j) gets blocks b = r*16 + 2j + {0,1},
    // r = 8i..8i+7  (16 independent L2 loads per thread).
    if (tid < 64) {
        const int i = tid >> 3, j = tid & 7;
        int pcnt = 0;
        #pragma unroll
        for (int rr = 0; rr < 8; rr++) {
            const int b = (8 * i + rr) * 16 + 2 * j;
            pcnt += g_blkcnt[b] + g_blkcnt[b + 1];
        }
        s_cond[tid] = (pcnt > 0 && pcnt < 64) ? 1.0f : 0.0f;
    }
    __syncthreads();

    // base sum from 1024 partials (double), 4 per thread
    double acc = (double)g_partial[tid]
               + (double)g_partial[tid + 256]
               + (double)g_partial[tid + 512]
               + (double)g_partial[tid + 768];

    // corner correction: 64 (i,j) x 64 batches, L2-hot pc reloads
    {
        const int ij = tid & 63;
        const int i  = ij >> 3, j = ij & 7;
        if (s_cond[ij] != 0.0f) {
            const int b0 = (tid >> 6) * 16;
            float csum = 0.0f;
            #pragma unroll 4
            for (int b = b0; b < b0 + 16; b++) {
                float p = pc[(size_t)b * 8192u + i * 128 + j];
                csum += __logf(p) - log1pf(-p);
            }
            acc += (double)csum;
        }
    }

    #pragma unroll
    for (int o = 16; o > 0; o >>= 1)
        acc += __shfl_down_sync(0xffffffffu, acc, o);
    if (lane == 0) s_red[wid] = acc;
    __syncthreads();
    if (tid == 0) {
        double total = 0.0;
        #pragma unroll
        for (int k = 0; k < 8; k++) total += s_red[k];
        out[0] = (float)(-total / (double)N_PC);
    }
}

extern "C" void kernel_launch(void* const* d_in, const int* in_sizes, int n_in,
                              void* d_out, int out_size) {
    const float* pc;
    const int*   tg;
    if (in_sizes[0] == N_PC) {
        pc = (const float*)d_in[0];
        tg = (const int*)  d_in[1];
    } else {
        pc = (const float*)d_in[1];
        tg = (const int*)  d_in[0];
    }
    fused_kernel<<<GRID, THREADS>>>((const float2*)pc, (const int4*)tg,
                                    pc, (float*)d_out);
}

// round 5
// speedup vs baseline: 1.5477x; 1.1131x over previous
#include <cuda_runtime.h>
#include <cuda_bf16.h>

// targets: (64, 512, 1024) int32; live region = [:64, :64, :] (16 MiB)
// pc:      (64, 1, 64, 128) float32 (2 MiB)
// loss = -(1/N) * [ sum log1p(-pc) + sum_corner cond(i,j)*(log pc - log1p(-pc)) ]
// cond(i,j) = (0 < count_ij < 64); count_ij over targets[8i:8i+8, 8j:8j+8, :].
// Early-exit: if ANY observed partial count >= 64, cond=0 is already decided.
// Each warp samples the first 512 ints of its patch (shared across the patch's
// 16 blocks -> L2 broadcast); sample >= 64 => skip the exact read (sentinel).

#define N_PC    524288
#define GRID    1024     // power of two: monotonic done-counter wraps cleanly
#define THREADS 256

__device__ int          g_blkcnt[GRID];   // per-block patch-partial count (plain store)
__device__ float        g_partial[GRID];  // per-block loss partial (plain store)
__device__ unsigned int g_done;           // monotonic arrival counter (zero-init at load)

__global__ __launch_bounds__(THREADS) void fused_kernel(
    const float2* __restrict__ pc2,
    const int4*   __restrict__ tg4,
    const float*  __restrict__ pc,
    float*        __restrict__ out)
{
    const int tid  = threadIdx.x;
    const int bid  = blockIdx.x;
    const int wid  = tid >> 5;
    const int lane = tid & 31;

    // ---- pc loss load (always needed) issued first
    const int idx = bid * THREADS + tid;            // 0..262143
    float2 v = pc2[idx];

    // ---- warp's half-row and its patch
    const int wg   = bid * 8 + wid;                 // 0..8191
    const int row  = wg >> 1;                       // 0..4095 (= r*64 + c)
    const int half = wg & 1;
    const int r    = row >> 6;                      // 0..63 (batch)
    const int c    = row & 63;                      // 0..63 (H)

    // ---- patch sample: first 512 ints of patch (r&~7, c&~7, w=0..511) = 2KB
    const int4* samp = tg4 + (size_t)(r & ~7) * 131072u + (size_t)(c & ~7) * 256u;
    int scnt = 0;
    #pragma unroll
    for (int k = 0; k < 4; k++) {
        int4 q = samp[lane + k * 32];
        scnt += (q.x == 2) + (q.y == 2) + (q.z == 2) + (q.w == 2);
    }
    scnt = __reduce_add_sync(0xffffffffu, scnt);    // warp-uniform, patch-uniform

    int cnt;
    if (scnt >= 64) {
        // cond=0 proven; sentinel keeps patch total >= 64 in the finalize.
        cnt = 1 << 17;                              // 8 warps -> block stores 1<<20
    } else {
        // exact fallback: read the warp's half-row (512 ints = 128 int4)
        const int4* base = tg4 + (size_t)r * 131072u + (size_t)c * 256u
                               + (size_t)half * 128u;
        int4 q0 = base[lane];
        int4 q1 = base[lane + 32];
        int4 q2 = base[lane + 64];
        int4 q3 = base[lane + 96];
        int t = (q0.x==2)+(q0.y==2)+(q0.z==2)+(q0.w==2)
              + (q1.x==2)+(q1.y==2)+(q1.z==2)+(q1.w==2)
              + (q2.x==2)+(q2.y==2)+(q2.z==2)+(q2.w==2)
              + (q3.x==2)+(q3.y==2)+(q3.z==2)+(q3.w==2);
        cnt = __reduce_add_sync(0xffffffffu, t);
    }

    // ---- pc partial (t=0 form)
    float s = log1pf(-v.x) + log1pf(-v.y);
    #pragma unroll
    for (int o = 16; o > 0; o >>= 1)
        s += __shfl_down_sync(0xffffffffu, s, o);

    __shared__ float sp[8];
    __shared__ int   sc[8];
    if (lane == 0) { sp[wid] = s; sc[wid] = cnt; }
    __syncthreads();
    if (tid == 0) {
        float bs = 0.0f; int bc = 0;
        #pragma unroll
        for (int k = 0; k < 8; k++) { bs += sp[k]; bc += sc[k]; }
        g_partial[bid] = bs;
        g_blkcnt[bid]  = bc;   // rows 4b..4b+3 all lie in ONE patch (i,j)
    }

    // ---- publish + arrive
    __threadfence();
    __syncthreads();
    __shared__ unsigned int s_last;
    if (tid == 0) {
        unsigned int old = atomicAdd(&g_done, 1u);
        s_last = ((old & (GRID - 1u)) == GRID - 1u) ? 1u : 0u;
    }
    __syncthreads();
    if (!s_last) return;
    __threadfence();

    // ================= last block: aggregate =================
    __shared__ float  s_cond[64];
    __shared__ double s_red[8];

    // patch counts -> cond. Patch (i,j) gets blocks b = (8i+rr)*16 + 2j + {0,1}.
    if (tid < 64) {
        const int i = tid >> 3, j = tid & 7;
        int pcnt = 0;
        #pragma unroll
        for (int rr = 0; rr < 8; rr++) {
            const int b = (8 * i + rr) * 16 + 2 * j;
            pcnt += g_blkcnt[b] + g_blkcnt[b + 1];
        }
        s_cond[tid] = (pcnt > 0 && pcnt < 64) ? 1.0f : 0.0f;
    }
    __syncthreads();

    // base sum from 1024 partials (double), 4 per thread
    double acc = (double)g_partial[tid]
               + (double)g_partial[tid + 256]
               + (double)g_partial[tid + 512]
               + (double)g_partial[tid + 768];

    // corner correction: 64 (i,j) x 64 batches, L2-hot pc reloads
    {
        const int ij = tid & 63;
        const int i  = ij >> 3, j = ij & 7;
        if (s_cond[ij] != 0.0f) {
            const int b0 = (tid >> 6) * 16;
            float csum = 0.0f;
            #pragma unroll 4
            for (int b = b0; b < b0 + 16; b++) {
                float p = pc[(size_t)b * 8192u + i * 128 + j];
                csum += __logf(p) - log1pf(-p);
            }
            acc += (double)csum;
        }
    }

    #pragma unroll
    for (int o = 16; o > 0; o >>= 1)
        acc += __shfl_down_sync(0xffffffffu, acc, o);
    if (lane == 0) s_red[wid] = acc;
    __syncthreads();
    if (tid == 0) {
        double total = 0.0;
        #pragma unroll
        for (int k = 0; k < 8; k++) total += s_red[k];
        out[0] = (float)(-total / (double)N_PC);
    }
}

extern "C" void kernel_launch(void* const* d_in, const int* in_sizes, int n_in,
                              void* d_out, int out_size) {
    const float* pc;
    const int*   tg;
    if (in_sizes[0] == N_PC) {
        pc = (const float*)d_in[0];
        tg = (const int*)  d_in[1];
    } else {
        pc = (const float*)d_in[1];
        tg = (const int*)  d_in[0];
    }
    fused_kernel<<<GRID, THREADS>>>((const float2*)pc, (const int4*)tg,
                                    pc, (float*)d_out);
}

// round 6
// speedup vs baseline: 1.7043x; 1.1012x over previous
#include <cuda_runtime.h>
#include <cuda_bf16.h>

// targets: (64, 512, 1024) int32; live region = [:64, :64, :] (16 MiB)
// pc:      (64, 1, 64, 128) float32 (2 MiB)
// loss = -(1/N) * [ sum log(1-pc) + sum_corner cond(i,j)*(log pc - log(1-pc)) ]
// cond(i,j) = (0 < count_ij < 64); count_ij over targets[8i:8i+8, 8j:8j+8, :].
//
// Early-exit: if ANY observed partial count >= 64, cond=0 is proven. Each warp
// samples the first 512 ints of its patch (L2-shared across the patch's blocks);
// sample >= 64 => sentinel, skip exact read. Fallback stays exact for any input.
//
// log trick: log1p(-p) == log(1-p) for p in (1e-4, 1-1e-4) to ~6e-8 abs;
// sum of logs = log of product -> ONE MUFU per 4 elements.

#define N_PC    524288
#define GRID    512      // power of two: monotonic done-counter wraps cleanly
#define THREADS 256

__device__ int          g_blkcnt[GRID];   // per-block patch-partial count (plain store)
__device__ float        g_partial[GRID];  // per-block loss partial (plain store)
__device__ unsigned int g_done;           // monotonic arrival counter (zero-init at load)

__global__ __launch_bounds__(THREADS) void fused_kernel(
    const float4* __restrict__ pc4,
    const int4*   __restrict__ tg4,
    const float*  __restrict__ pc,
    float*        __restrict__ out)
{
    const int tid  = threadIdx.x;
    const int bid  = blockIdx.x;
    const int wid  = tid >> 5;
    const int lane = tid & 31;

    // ---- pc loss load (always needed) issued first
    const int idx = bid * THREADS + tid;            // 0..131071
    float4 v = pc4[idx];

    // ---- warp's targets row and its patch
    const int row = bid * 8 + wid;                  // 0..4095 (= r*64 + c)
    const int r   = row >> 6;                       // 0..63 (batch)
    const int c   = row & 63;                       // 0..63 (H)

    // ---- patch sample: first 512 ints of patch (r&~7, c&~7, w=0..511) = 2KB
    const int4* samp = tg4 + (size_t)(r & ~7) * 131072u + (size_t)(c & ~7) * 256u;
    int scnt = 0;
    #pragma unroll
    for (int k = 0; k < 4; k++) {
        int4 q = samp[lane + k * 32];
        scnt += (q.x == 2) + (q.y == 2) + (q.z == 2) + (q.w == 2);
    }
    scnt = __reduce_add_sync(0xffffffffu, scnt);    // warp-uniform, patch-uniform

    int cnt;
    if (scnt >= 64) {
        cnt = 1 << 17;  // cond=0 proven; sentinel keeps patch total >= 64
    } else {
        // exact fallback: read the warp's full row (1024 ints = 256 int4)
        const int4* base = tg4 + (size_t)r * 131072u + (size_t)c * 256u;
        int t = 0;
        #pragma unroll
        for (int k = 0; k < 8; k++) {
            int4 q = base[lane + k * 32];
            t += (q.x == 2) + (q.y == 2) + (q.z == 2) + (q.w == 2);
        }
        cnt = __reduce_add_sync(0xffffffffu, t);
    }

    // ---- pc partial: one log of the product of (1-p) over 4 elements
    float prod = (1.0f - v.x) * (1.0f - v.y) * (1.0f - v.z) * (1.0f - v.w);
    float s = __logf(prod);
    #pragma unroll
    for (int o = 16; o > 0; o >>= 1)
        s += __shfl_down_sync(0xffffffffu, s, o);

    __shared__ float sp[8];
    __shared__ int   sc[8];
    if (lane == 0) { sp[wid] = s; sc[wid] = cnt; }
    __syncthreads();
    if (tid == 0) {
        float bs = 0.0f; int bc = 0;
        #pragma unroll
        for (int k = 0; k < 8; k++) { bs += sp[k]; bc += sc[k]; }
        g_partial[bid] = bs;
        g_blkcnt[bid]  = bc;   // all 8 rows of this block lie in ONE patch (i,j)
    }

    // ---- publish + arrive
    __threadfence();
    __syncthreads();
    __shared__ unsigned int s_last;
    if (tid == 0) {
        unsigned int old = atomicAdd(&g_done, 1u);
        s_last = ((old & (GRID - 1u)) == GRID - 1u) ? 1u : 0u;
    }
    __syncthreads();
    if (!s_last) return;
    __threadfence();

    // ================= last block: aggregate =================
    __shared__ float  s_cond[64];
    __shared__ double s_red[8];

    // patch (i,j) -> blocks b = 8*(8i+rr) + j, rr = 0..7
    if (tid < 64) {
        const int i = tid >> 3, j = tid & 7;
        int pcnt = 0;
        #pragma unroll
        for (int rr = 0; rr < 8; rr++)
            pcnt += g_blkcnt[8 * (8 * i + rr) + j];
        s_cond[tid] = (pcnt > 0 && pcnt < 64) ? 1.0f : 0.0f;
    }
    __syncthreads();

    // base sum from 512 partials (double), 2 per thread
    double acc = (double)g_partial[tid] + (double)g_partial[tid + 256];

    // corner correction: 64 (i,j) x 64 batches, L2-hot pc reloads
    {
        const int ij = tid & 63;
        const int i  = ij >> 3, j = ij & 7;
        if (s_cond[ij] != 0.0f) {
            const int b0 = (tid >> 6) * 16;
            float csum = 0.0f;
            #pragma unroll 4
            for (int b = b0; b < b0 + 16; b++) {
                float p = pc[(size_t)b * 8192u + i * 128 + j];
                csum += __logf(p / (1.0f - p));
            }
            acc += (double)csum;
        }
    }

    #pragma unroll
    for (int o = 16; o > 0; o >>= 1)
        acc += __shfl_down_sync(0xffffffffu, acc, o);
    if (lane == 0) s_red[wid] = acc;
    __syncthreads();
    if (tid == 0) {
        double total = 0.0;
        #pragma unroll
        for (int k = 0; k < 8; k++) total += s_red[k];
        out[0] = (float)(-total / (double)N_PC);
    }
}

extern "C" void kernel_launch(void* const* d_in, const int* in_sizes, int n_in,
                              void* d_out, int out_size) {
    const float* pc;
    const int*   tg;
    if (in_sizes[0] == N_PC) {
        pc = (const float*)d_in[0];
        tg = (const int*)  d_in[1];
    } else {
        pc = (const float*)d_in[1];
        tg = (const int*)  d_in[0];
    }
    fused_kernel<<<GRID, THREADS>>>((const float4*)pc, (const int4*)tg,
                                    pc, (float*)d_out);
}